// round 8
// baseline (speedup 1.0000x reference)
#include <cuda_runtime.h>
#include <math.h>

#define NB     32
#define LSEQ   4096
#define DMODEL 16
#define DIN    32
#define NST    16
#define SEG    64
#define NSEG   (LSEQ / SEG)      // 64
#define NTOK   (NB * LSEQ)       // 131072
#define LANES  (DIN * NST)       // 512

// ---------------- device scratch (static: no allocations in kernel_launch) ----
__device__ float  g_h  [NTOK * DMODEL];   // residual stream
__device__ float  g_xin[NTOK * DIN];      // pre-conv branch
__device__ float  g_sz [NTOK * DIN];      // silu(z)
__device__ float  g_xc [NTOK * DIN];      // post-conv silu
__device__ float2 g_ddx[NTOK * DIN];      // (delta, delta*xc) per (tok, e)
__device__ float2 g_bc [NTOK * NST];      // (B, C) per (tok, n)
__device__ float  g_y  [NTOK * DIN];      // scan output
__device__ float  g_P  [NB * NSEG * LANES];
__device__ float  g_q  [NB * NSEG * LANES];
__device__ float  g_ci [NB * NSEG * LANES];

__device__ __forceinline__ float silu_f(float x) {
    return x * (1.0f / (1.0f + __expf(-x)));
}
__device__ __forceinline__ float softplus_f(float x) {
    return fmaxf(x, 0.0f) + log1pf(__expf(-fabsf(x)));
}

// ---------------- lin_in: h = x @ W.T + b   (64 -> 16) ----------------------
__global__ __launch_bounds__(128)
void k_lin_in(const float* __restrict__ x, const float* __restrict__ W,
              const float* __restrict__ bvec) {
    __shared__ float4 sW[DMODEL * 16];   // 16 rows x 64 cols
    __shared__ float  sb[DMODEL];
    int tid = threadIdx.x;
    for (int i = tid; i < DMODEL * 16; i += 128) sW[i] = ((const float4*)W)[i];
    if (tid < DMODEL) sb[tid] = bvec[tid];
    __syncthreads();

    int tok = blockIdx.x * 128 + tid;
    const float4* xr = (const float4*)(x + (size_t)tok * 64);
    float4 xv[16];
#pragma unroll
    for (int i = 0; i < 16; i++) xv[i] = xr[i];

    float4* ho = (float4*)(g_h + (size_t)tok * DMODEL);
#pragma unroll
    for (int d4 = 0; d4 < 4; d4++) {
        float a[4];
#pragma unroll
        for (int q = 0; q < 4; q++) {
            int d = d4 * 4 + q;
            float s = sb[d];
#pragma unroll
            for (int j = 0; j < 16; j++) {
                float4 w = sW[d * 16 + j];
                s += xv[j].x * w.x + xv[j].y * w.y + xv[j].z * w.z + xv[j].w * w.w;
            }
            a[q] = s;
        }
        ho[d4] = make_float4(a[0], a[1], a[2], a[3]);
    }
}

// ---------------- P1: rmsnorm + in_proj (16 -> 64), split xin / silu(z) -----
__global__ __launch_bounds__(128)
void k_p1(const float* __restrict__ norm_w, const float* __restrict__ Wi) {
    __shared__ float4 sW[64 * 4];        // 64 rows x 16 cols
    __shared__ float  snw[DMODEL];
    int tid = threadIdx.x;
    for (int i = tid; i < 64 * 4; i += 128) sW[i] = ((const float4*)Wi)[i];
    if (tid < DMODEL) snw[tid] = norm_w[tid];
    __syncthreads();

    int tok = blockIdx.x * 128 + tid;
    const float4* hr = (const float4*)(g_h + (size_t)tok * DMODEL);
    float hv[16];
#pragma unroll
    for (int i = 0; i < 4; i++) {
        float4 v = hr[i];
        hv[4 * i] = v.x; hv[4 * i + 1] = v.y; hv[4 * i + 2] = v.z; hv[4 * i + 3] = v.w;
    }
    float ss = 0.f;
#pragma unroll
    for (int d = 0; d < 16; d++) ss += hv[d] * hv[d];
    float sc = rsqrtf(ss * (1.0f / 16.0f) + 1e-5f);
    float xn[16];
#pragma unroll
    for (int d = 0; d < 16; d++) xn[d] = hv[d] * snw[d];

    float4* xin_o = (float4*)(g_xin + (size_t)tok * DIN);
    float4* sz_o  = (float4*)(g_sz  + (size_t)tok * DIN);
    float buf[4];
#pragma unroll
    for (int o = 0; o < 64; o++) {
        float s = 0.f;
#pragma unroll
        for (int j = 0; j < 4; j++) {
            float4 w = sW[o * 4 + j];
            s += xn[4 * j] * w.x + xn[4 * j + 1] * w.y + xn[4 * j + 2] * w.z + xn[4 * j + 3] * w.w;
        }
        s *= sc;
        if (o < 32) {
            buf[o & 3] = s;
            if ((o & 3) == 3) xin_o[o >> 2] = make_float4(buf[0], buf[1], buf[2], buf[3]);
        } else {
            buf[o & 3] = silu_f(s);
            if ((o & 3) == 3) sz_o[(o - 32) >> 2] = make_float4(buf[0], buf[1], buf[2], buf[3]);
        }
    }
}

// ---------------- P2: causal conv4 + silu + x_proj + softplus(delta) --------
__global__ __launch_bounds__(128)
void k_p2(const float* __restrict__ Wx, const float* __restrict__ cw,
          const float* __restrict__ cb, const float* __restrict__ dtw,
          const float* __restrict__ dtb) {
    __shared__ float4 s_xin4[131 * 8];           // 131 rows x 32 floats
    __shared__ float4 sWx4[33 * 8];              // 33 rows x 32 floats
    __shared__ float  scw[DIN * 4], scb[DIN], sdtw[DIN], sdtb[DIN];
    float* s_xin = (float*)s_xin4;
    float* sWx   = (float*)sWx4;

    int tid = threadIdx.x;
    int b = blockIdx.y;
    int t0 = blockIdx.x * 128;

    for (int i = tid; i < 33 * 8; i += 128) sWx4[i] = ((const float4*)Wx)[i];
    for (int i = tid; i < DIN * 4; i += 128) scw[i] = cw[i];
    if (tid < DIN) { scb[tid] = cb[tid]; sdtw[tid] = dtw[tid]; sdtb[tid] = dtb[tid]; }

    // stage xin rows [t0-3, t0+127] (zero-pad t<0)
    const float4* gx = (const float4*)(g_xin + ((long long)b * LSEQ + t0 - 3) * DIN);
    for (int i = tid; i < 131 * 8; i += 128) {
        float4 v;
        if (t0 == 0 && i < 24) v = make_float4(0.f, 0.f, 0.f, 0.f);
        else                   v = gx[i];
        s_xin4[i] = v;
    }
    __syncthreads();

    int t = t0 + tid;
    float xc[32];
#pragma unroll
    for (int e = 0; e < 32; e++) {
        float v = scb[e];
#pragma unroll
        for (int k = 0; k < 4; k++) v += s_xin[(tid + k) * DIN + e] * scw[e * 4 + k];
        xc[e] = silu_f(v);
    }
    size_t base = (size_t)b * LSEQ + t;

    float4* xco = (float4*)(g_xc + base * DIN);
#pragma unroll
    for (int i = 0; i < 8; i++)
        xco[i] = make_float4(xc[4 * i], xc[4 * i + 1], xc[4 * i + 2], xc[4 * i + 3]);

    float dbc[33];
#pragma unroll
    for (int o = 0; o < 33; o++) {
        float s = 0.f;
        const float4* wr = (const float4*)(sWx + o * 32);
#pragma unroll
        for (int j = 0; j < 8; j++) {
            float4 w = wr[j];
            s += xc[4 * j] * w.x + xc[4 * j + 1] * w.y + xc[4 * j + 2] * w.z + xc[4 * j + 3] * w.w;
        }
        dbc[o] = s;
    }

    float4* ddxo = (float4*)(g_ddx + base * DIN);
#pragma unroll
    for (int e = 0; e < 32; e += 2) {
        float d0 = softplus_f(dbc[0] * sdtw[e]     + sdtb[e]);
        float d1 = softplus_f(dbc[0] * sdtw[e + 1] + sdtb[e + 1]);
        ddxo[e >> 1] = make_float4(d0, d0 * xc[e], d1, d1 * xc[e + 1]);
    }
    float4* bco = (float4*)(g_bc + base * NST);
#pragma unroll
    for (int n = 0; n < 16; n += 2)
        bco[n >> 1] = make_float4(dbc[1 + n], dbc[17 + n], dbc[2 + n], dbc[18 + n]);
}

// ---------------- scan pass 1: per-segment affine map (P, q) ----------------
__global__ __launch_bounds__(512)
void k_scan1(const float* __restrict__ A_log) {
    __shared__ float4 s_ddx4[SEG * DIN / 2];    // float2[SEG*DIN]
    __shared__ float4 s_bc4 [SEG * NST / 2];
    float2* s_ddx = (float2*)s_ddx4;
    float2* s_bc  = (float2*)s_bc4;

    int tid = threadIdx.x;
    int b = blockIdx.y, s = blockIdx.x;
    size_t base = (size_t)b * LSEQ + (size_t)s * SEG;

    const float4* gd = (const float4*)(g_ddx + base * DIN);
#pragma unroll
    for (int i = tid; i < SEG * DIN / 2; i += 512) s_ddx4[i] = gd[i];
    const float4* gb = (const float4*)(g_bc + base * NST);
#pragma unroll
    for (int i = tid; i < SEG * NST / 2; i += 512) s_bc4[i] = gb[i];

    int e = tid >> 4, n = tid & 15;
    float Aen = -expf(A_log[e * NST + n]);
    __syncthreads();

    float h = 0.f, P = 1.f;
#pragma unroll 4
    for (int t = 0; t < SEG; t++) {
        float2 dd = s_ddx[t * DIN + e];
        float2 bc = s_bc[t * NST + n];
        float dA = __expf(dd.x * Aen);
        h = fmaf(dA, h, dd.y * bc.x);
        P *= dA;
    }
    int li = (b * NSEG + s) * LANES + tid;
    g_P[li] = P;
    g_q[li] = h;
}

// ---------------- combine carries across segments ---------------------------
__global__ __launch_bounds__(512)
void k_comb() {
    int b = blockIdx.x, tid = threadIdx.x;
    float h = 0.f;
    for (int s = 0; s < NSEG; s++) {
        int li = (b * NSEG + s) * LANES + tid;
        g_ci[li] = h;
        h = g_P[li] * h + g_q[li];
    }
}

// ---------------- scan pass 2: full scan with carry, emit y -----------------
__global__ __launch_bounds__(512)
void k_scan2(const float* __restrict__ A_log) {
    __shared__ float4 s_ddx4[SEG * DIN / 2];
    __shared__ float4 s_bc4 [SEG * NST / 2];
    __shared__ float4 s_y4  [SEG * DIN / 4];
    float2* s_ddx = (float2*)s_ddx4;
    float2* s_bc  = (float2*)s_bc4;
    float*  s_y   = (float*)s_y4;

    int tid = threadIdx.x;
    int b = blockIdx.y, s = blockIdx.x;
    size_t base = (size_t)b * LSEQ + (size_t)s * SEG;

    const float4* gd = (const float4*)(g_ddx + base * DIN);
#pragma unroll
    for (int i = tid; i < SEG * DIN / 2; i += 512) s_ddx4[i] = gd[i];
    const float4* gb = (const float4*)(g_bc + base * NST);
#pragma unroll
    for (int i = tid; i < SEG * NST / 2; i += 512) s_bc4[i] = gb[i];

    int e = tid >> 4, n = tid & 15;
    float Aen = -expf(A_log[e * NST + n]);
    float h = g_ci[(b * NSEG + s) * LANES + tid];
    __syncthreads();

#pragma unroll 2
    for (int t = 0; t < SEG; t++) {
        float2 dd = s_ddx[t * DIN + e];
        float2 bc = s_bc[t * NST + n];
        float dA = __expf(dd.x * Aen);
        h = fmaf(dA, h, dd.y * bc.x);
        float p = h * bc.y;
        p += __shfl_xor_sync(0xffffffffu, p, 8);
        p += __shfl_xor_sync(0xffffffffu, p, 4);
        p += __shfl_xor_sync(0xffffffffu, p, 2);
        p += __shfl_xor_sync(0xffffffffu, p, 1);
        if (n == 0) s_y[t * DIN + e] = p;
    }
    __syncthreads();

    float4* gy = (float4*)(g_y + base * DIN);
#pragma unroll
    for (int i = tid; i < SEG * DIN / 4; i += 512) gy[i] = s_y4[i];
}

// ---------------- post: (y + D*xc) * silu(z) @ Wo.T + residual --------------
__global__ __launch_bounds__(128)
void k_post(const float* __restrict__ Wo, const float* __restrict__ Dv) {
    __shared__ float4 sWo4[DMODEL * 8];   // 16 rows x 32 cols
    __shared__ float  sD[DIN];
    float* sWo = (float*)sWo4;
    int tid = threadIdx.x;
    for (int i = tid; i < DMODEL * 8; i += 128) sWo4[i] = ((const float4*)Wo)[i];
    if (tid < DIN) sD[tid] = Dv[tid];
    __syncthreads();

    int tok = blockIdx.x * 128 + tid;
    size_t b32 = (size_t)tok * DIN;
    const float4* yr  = (const float4*)(g_y  + b32);
    const float4* xcr = (const float4*)(g_xc + b32);
    const float4* szr = (const float4*)(g_sz + b32);
    float u[32];
#pragma unroll
    for (int i = 0; i < 8; i++) {
        float4 y = yr[i], xc = xcr[i], sz = szr[i];
        u[4 * i + 0] = (y.x + sD[4 * i + 0] * xc.x) * sz.x;
        u[4 * i + 1] = (y.y + sD[4 * i + 1] * xc.y) * sz.y;
        u[4 * i + 2] = (y.z + sD[4 * i + 2] * xc.z) * sz.z;
        u[4 * i + 3] = (y.w + sD[4 * i + 3] * xc.w) * sz.w;
    }
    float4* hr = (float4*)(g_h + (size_t)tok * DMODEL);
#pragma unroll
    for (int d4 = 0; d4 < 4; d4++) {
        float4 hv = hr[d4];
        float a[4] = {hv.x, hv.y, hv.z, hv.w};
#pragma unroll
        for (int q = 0; q < 4; q++) {
            int d = d4 * 4 + q;
            float sacc = 0.f;
            const float4* wr = (const float4*)(sWo + d * 32);
#pragma unroll
            for (int j = 0; j < 8; j++) {
                float4 w = wr[j];
                sacc += u[4 * j] * w.x + u[4 * j + 1] * w.y + u[4 * j + 2] * w.z + u[4 * j + 3] * w.w;
            }
            a[q] += sacc;
        }
        hr[d4] = make_float4(a[0], a[1], a[2], a[3]);
    }
}

// ---------------- final: out = h @ w.T + b ----------------------------------
__global__ __launch_bounds__(128)
void k_final(const float* __restrict__ w, const float* __restrict__ bb,
             float* __restrict__ out) {
    __shared__ float4 sw4[4];
    __shared__ float  sb0;
    if (threadIdx.x < 4) sw4[threadIdx.x] = ((const float4*)w)[threadIdx.x];
    if (threadIdx.x == 0) sb0 = bb[0];
    __syncthreads();
    int tok = blockIdx.x * 128 + threadIdx.x;
    const float4* hr = (const float4*)(g_h + (size_t)tok * DMODEL);
    float s = sb0;
#pragma unroll
    for (int i = 0; i < 4; i++) {
        float4 v = hr[i];
        float4 w4 = sw4[i];
        s += v.x * w4.x + v.y * w4.y + v.z * w4.z + v.w * w4.w;
    }
    out[tok] = s;
}

// ---------------- driver -----------------------------------------------------
extern "C" void kernel_launch(void* const* d_in, const int* in_sizes, int n_in,
                              void* d_out, int out_size) {
    const float* x = (const float*)d_in[0];

    k_lin_in<<<NTOK / 128, 128>>>(x, (const float*)d_in[1], (const float*)d_in[2]);

    for (int layer = 0; layer < 2; layer++) {
        int o = 3 + layer * 10;
        const float* norm_w = (const float*)d_in[o + 0];
        const float* in_w   = (const float*)d_in[o + 1];
        const float* conv_w = (const float*)d_in[o + 2];
        const float* conv_b = (const float*)d_in[o + 3];
        const float* xp_w   = (const float*)d_in[o + 4];
        const float* dt_w   = (const float*)d_in[o + 5];
        const float* dt_b   = (const float*)d_in[o + 6];
        const float* A_log  = (const float*)d_in[o + 7];
        const float* Dv     = (const float*)d_in[o + 8];
        const float* out_w  = (const float*)d_in[o + 9];

        k_p1<<<NTOK / 128, 128>>>(norm_w, in_w);
        k_p2<<<dim3(LSEQ / 128, NB), 128>>>(xp_w, conv_w, conv_b, dt_w, dt_b);
        k_scan1<<<dim3(NSEG, NB), 512>>>(A_log);
        k_comb<<<NB, 512>>>();
        k_scan2<<<dim3(NSEG, NB), 512>>>(A_log);
        k_post<<<NTOK / 128, 128>>>(out_w, Dv);
    }

    k_final<<<NTOK / 128, 128>>>((const float*)d_in[23], (const float*)d_in[24],
                                 (float*)d_out);
}

// round 12
// speedup vs baseline: 1.0025x; 1.0025x over previous
#include <cuda_runtime.h>
#include <math.h>

#define NB     32
#define LSEQ   4096
#define DMODEL 16
#define DIN    32
#define NST    16
#define SEG    64
#define NSEG   (LSEQ / SEG)      // 64
#define NTOK   (NB * LSEQ)       // 131072
#define LANES  (DIN * NST)       // 512

// ---------------- device scratch (static: no allocations in kernel_launch) ----
__device__ float  g_h  [NTOK * DMODEL];   // residual stream
__device__ float  g_xin[NTOK * DIN];      // pre-conv branch
__device__ float  g_sz [NTOK * DIN];      // silu(z)
__device__ float  g_xc [NTOK * DIN];      // post-conv silu
__device__ float2 g_ddx[NTOK * DIN];      // (delta, delta*xc) per (tok, e)
__device__ float2 g_bc [NTOK * NST];      // (B, C) per (tok, n)
__device__ float  g_y  [NTOK * DIN];      // scan output
__device__ float  g_P  [NB * NSEG * LANES];
__device__ float  g_q  [NB * NSEG * LANES];
__device__ float  g_ci [NB * NSEG * LANES];

__device__ __forceinline__ float silu_f(float x) {
    return x * (1.0f / (1.0f + __expf(-x)));
}
__device__ __forceinline__ float softplus_f(float x) {
    return fmaxf(x, 0.0f) + log1pf(__expf(-fabsf(x)));
}

// ---------------- lin_in: h = x @ W.T + b   (64 -> 16) ----------------------
__global__ __launch_bounds__(128)
void k_lin_in(const float* __restrict__ x, const float* __restrict__ W,
              const float* __restrict__ bvec) {
    __shared__ float4 sW[DMODEL * 16];   // 16 rows x 64 cols
    __shared__ float  sb[DMODEL];
    int tid = threadIdx.x;
    for (int i = tid; i < DMODEL * 16; i += 128) sW[i] = ((const float4*)W)[i];
    if (tid < DMODEL) sb[tid] = bvec[tid];
    __syncthreads();

    int tok = blockIdx.x * 128 + tid;
    const float4* xr = (const float4*)(x + (size_t)tok * 64);
    float4 xv[16];
#pragma unroll
    for (int i = 0; i < 16; i++) xv[i] = xr[i];

    float4* ho = (float4*)(g_h + (size_t)tok * DMODEL);
#pragma unroll
    for (int d4 = 0; d4 < 4; d4++) {
        float a[4];
#pragma unroll
        for (int q = 0; q < 4; q++) {
            int d = d4 * 4 + q;
            float s = sb[d];
#pragma unroll
            for (int j = 0; j < 16; j++) {
                float4 w = sW[d * 16 + j];
                s += xv[j].x * w.x + xv[j].y * w.y + xv[j].z * w.z + xv[j].w * w.w;
            }
            a[q] = s;
        }
        ho[d4] = make_float4(a[0], a[1], a[2], a[3]);
    }
}

// ---------------- P1: rmsnorm + in_proj (16 -> 64), split xin / silu(z) -----
__global__ __launch_bounds__(128)
void k_p1(const float* __restrict__ norm_w, const float* __restrict__ Wi) {
    __shared__ float4 sW[64 * 4];        // 64 rows x 16 cols
    __shared__ float  snw[DMODEL];
    int tid = threadIdx.x;
    for (int i = tid; i < 64 * 4; i += 128) sW[i] = ((const float4*)Wi)[i];
    if (tid < DMODEL) snw[tid] = norm_w[tid];
    __syncthreads();

    int tok = blockIdx.x * 128 + tid;
    const float4* hr = (const float4*)(g_h + (size_t)tok * DMODEL);
    float hv[16];
#pragma unroll
    for (int i = 0; i < 4; i++) {
        float4 v = hr[i];
        hv[4 * i] = v.x; hv[4 * i + 1] = v.y; hv[4 * i + 2] = v.z; hv[4 * i + 3] = v.w;
    }
    float ss = 0.f;
#pragma unroll
    for (int d = 0; d < 16; d++) ss += hv[d] * hv[d];
    float sc = rsqrtf(ss * (1.0f / 16.0f) + 1e-5f);
    float xn[16];
#pragma unroll
    for (int d = 0; d < 16; d++) xn[d] = hv[d] * snw[d];

    float4* xin_o = (float4*)(g_xin + (size_t)tok * DIN);
    float4* sz_o  = (float4*)(g_sz  + (size_t)tok * DIN);
    float buf[4];
#pragma unroll
    for (int o = 0; o < 64; o++) {
        float s = 0.f;
#pragma unroll
        for (int j = 0; j < 4; j++) {
            float4 w = sW[o * 4 + j];
            s += xn[4 * j] * w.x + xn[4 * j + 1] * w.y + xn[4 * j + 2] * w.z + xn[4 * j + 3] * w.w;
        }
        s *= sc;
        if (o < 32) {
            buf[o & 3] = s;
            if ((o & 3) == 3) xin_o[o >> 2] = make_float4(buf[0], buf[1], buf[2], buf[3]);
        } else {
            buf[o & 3] = silu_f(s);
            if ((o & 3) == 3) sz_o[(o - 32) >> 2] = make_float4(buf[0], buf[1], buf[2], buf[3]);
        }
    }
}

// ---------------- P2: causal conv4 + silu + x_proj + softplus(delta) --------
__global__ __launch_bounds__(128)
void k_p2(const float* __restrict__ Wx, const float* __restrict__ cw,
          const float* __restrict__ cb, const float* __restrict__ dtw,
          const float* __restrict__ dtb) {
    __shared__ float4 s_xin4[131 * 8];           // 131 rows x 32 floats
    __shared__ float4 sWx4[33 * 8];              // 33 rows x 32 floats
    __shared__ float  scw[DIN * 4], scb[DIN], sdtw[DIN], sdtb[DIN];
    float* s_xin = (float*)s_xin4;
    float* sWx   = (float*)sWx4;

    int tid = threadIdx.x;
    int b = blockIdx.y;
    int t0 = blockIdx.x * 128;

    for (int i = tid; i < 33 * 8; i += 128) sWx4[i] = ((const float4*)Wx)[i];
    for (int i = tid; i < DIN * 4; i += 128) scw[i] = cw[i];
    if (tid < DIN) { scb[tid] = cb[tid]; sdtw[tid] = dtw[tid]; sdtb[tid] = dtb[tid]; }

    // stage xin rows [t0-3, t0+127] (zero-pad t<0)
    const float4* gx = (const float4*)(g_xin + ((long long)b * LSEQ + t0 - 3) * DIN);
    for (int i = tid; i < 131 * 8; i += 128) {
        float4 v;
        if (t0 == 0 && i < 24) v = make_float4(0.f, 0.f, 0.f, 0.f);
        else                   v = gx[i];
        s_xin4[i] = v;
    }
    __syncthreads();

    int t = t0 + tid;
    float xc[32];
#pragma unroll
    for (int e = 0; e < 32; e++) {
        float v = scb[e];
#pragma unroll
        for (int k = 0; k < 4; k++) v += s_xin[(tid + k) * DIN + e] * scw[e * 4 + k];
        xc[e] = silu_f(v);
    }
    size_t base = (size_t)b * LSEQ + t;

    float4* xco = (float4*)(g_xc + base * DIN);
#pragma unroll
    for (int i = 0; i < 8; i++)
        xco[i] = make_float4(xc[4 * i], xc[4 * i + 1], xc[4 * i + 2], xc[4 * i + 3]);

    float dbc[33];
#pragma unroll
    for (int o = 0; o < 33; o++) {
        float s = 0.f;
        const float4* wr = (const float4*)(sWx + o * 32);
#pragma unroll
        for (int j = 0; j < 8; j++) {
            float4 w = wr[j];
            s += xc[4 * j] * w.x + xc[4 * j + 1] * w.y + xc[4 * j + 2] * w.z + xc[4 * j + 3] * w.w;
        }
        dbc[o] = s;
    }

    float4* ddxo = (float4*)(g_ddx + base * DIN);
#pragma unroll
    for (int e = 0; e < 32; e += 2) {
        float d0 = softplus_f(dbc[0] * sdtw[e]     + sdtb[e]);
        float d1 = softplus_f(dbc[0] * sdtw[e + 1] + sdtb[e + 1]);
        ddxo[e >> 1] = make_float4(d0, d0 * xc[e], d1, d1 * xc[e + 1]);
    }
    float4* bco = (float4*)(g_bc + base * NST);
#pragma unroll
    for (int n = 0; n < 16; n += 2)
        bco[n >> 1] = make_float4(dbc[1 + n], dbc[17 + n], dbc[2 + n], dbc[18 + n]);
}

// ---------------- scan pass 1: per-segment affine map (P, q) ----------------
__global__ __launch_bounds__(512)
void k_scan1(const float* __restrict__ A_log) {
    __shared__ float4 s_ddx4[SEG * DIN / 2];    // float2[SEG*DIN]
    __shared__ float4 s_bc4 [SEG * NST / 2];
    float2* s_ddx = (float2*)s_ddx4;
    float2* s_bc  = (float2*)s_bc4;

    int tid = threadIdx.x;
    int b = blockIdx.y, s = blockIdx.x;
    size_t base = (size_t)b * LSEQ + (size_t)s * SEG;

    const float4* gd = (const float4*)(g_ddx + base * DIN);
#pragma unroll
    for (int i = tid; i < SEG * DIN / 2; i += 512) s_ddx4[i] = gd[i];
    const float4* gb = (const float4*)(g_bc + base * NST);
#pragma unroll
    for (int i = tid; i < SEG * NST / 2; i += 512) s_bc4[i] = gb[i];

    int e = tid >> 4, n = tid & 15;
    float Aen = -expf(A_log[e * NST + n]);
    __syncthreads();

    float h = 0.f, P = 1.f;
#pragma unroll 4
    for (int t = 0; t < SEG; t++) {
        float2 dd = s_ddx[t * DIN + e];
        float2 bc = s_bc[t * NST + n];
        float dA = __expf(dd.x * Aen);
        h = fmaf(dA, h, dd.y * bc.x);
        P *= dA;
    }
    int li = (b * NSEG + s) * LANES + tid;
    g_P[li] = P;
    g_q[li] = h;
}

// ---------------- combine carries across segments ---------------------------
__global__ __launch_bounds__(512)
void k_comb() {
    int b = blockIdx.x, tid = threadIdx.x;
    float h = 0.f;
    for (int s = 0; s < NSEG; s++) {
        int li = (b * NSEG + s) * LANES + tid;
        g_ci[li] = h;
        h = g_P[li] * h + g_q[li];
    }
}

// ---------------- scan pass 2: full scan with carry, emit y -----------------
__global__ __launch_bounds__(512)
void k_scan2(const float* __restrict__ A_log) {
    __shared__ float4 s_ddx4[SEG * DIN / 2];
    __shared__ float4 s_bc4 [SEG * NST / 2];
    __shared__ float4 s_y4  [SEG * DIN / 4];
    float2* s_ddx = (float2*)s_ddx4;
    float2* s_bc  = (float2*)s_bc4;
    float*  s_y   = (float*)s_y4;

    int tid = threadIdx.x;
    int b = blockIdx.y, s = blockIdx.x;
    size_t base = (size_t)b * LSEQ + (size_t)s * SEG;

    const float4* gd = (const float4*)(g_ddx + base * DIN);
#pragma unroll
    for (int i = tid; i < SEG * DIN / 2; i += 512) s_ddx4[i] = gd[i];
    const float4* gb = (const float4*)(g_bc + base * NST);
#pragma unroll
    for (int i = tid; i < SEG * NST / 2; i += 512) s_bc4[i] = gb[i];

    int e = tid >> 4, n = tid & 15;
    float Aen = -expf(A_log[e * NST + n]);
    float h = g_ci[(b * NSEG + s) * LANES + tid];
    __syncthreads();

#pragma unroll 2
    for (int t = 0; t < SEG; t++) {
        float2 dd = s_ddx[t * DIN + e];
        float2 bc = s_bc[t * NST + n];
        float dA = __expf(dd.x * Aen);
        h = fmaf(dA, h, dd.y * bc.x);
        float p = h * bc.y;
        p += __shfl_xor_sync(0xffffffffu, p, 8);
        p += __shfl_xor_sync(0xffffffffu, p, 4);
        p += __shfl_xor_sync(0xffffffffu, p, 2);
        p += __shfl_xor_sync(0xffffffffu, p, 1);
        if (n == 0) s_y[t * DIN + e] = p;
    }
    __syncthreads();

    float4* gy = (float4*)(g_y + base * DIN);
#pragma unroll
    for (int i = tid; i < SEG * DIN / 4; i += 512) gy[i] = s_y4[i];
}

// ---------------- post: (y + D*xc) * silu(z) @ Wo.T + residual --------------
__global__ __launch_bounds__(128)
void k_post(const float* __restrict__ Wo, const float* __restrict__ Dv) {
    __shared__ float4 sWo4[DMODEL * 8];   // 16 rows x 32 cols
    __shared__ float  sD[DIN];
    float* sWo = (float*)sWo4;
    int tid = threadIdx.x;
    for (int i = tid; i < DMODEL * 8; i += 128) sWo4[i] = ((const float4*)Wo)[i];
    if (tid < DIN) sD[tid] = Dv[tid];
    __syncthreads();

    int tok = blockIdx.x * 128 + tid;
    size_t b32 = (size_t)tok * DIN;
    const float4* yr  = (const float4*)(g_y  + b32);
    const float4* xcr = (const float4*)(g_xc + b32);
    const float4* szr = (const float4*)(g_sz + b32);
    float u[32];
#pragma unroll
    for (int i = 0; i < 8; i++) {
        float4 y = yr[i], xc = xcr[i], sz = szr[i];
        u[4 * i + 0] = (y.x + sD[4 * i + 0] * xc.x) * sz.x;
        u[4 * i + 1] = (y.y + sD[4 * i + 1] * xc.y) * sz.y;
        u[4 * i + 2] = (y.z + sD[4 * i + 2] * xc.z) * sz.z;
        u[4 * i + 3] = (y.w + sD[4 * i + 3] * xc.w) * sz.w;
    }
    float4* hr = (float4*)(g_h + (size_t)tok * DMODEL);
#pragma unroll
    for (int d4 = 0; d4 < 4; d4++) {
        float4 hv = hr[d4];
        float a[4] = {hv.x, hv.y, hv.z, hv.w};
#pragma unroll
        for (int q = 0; q < 4; q++) {
            int d = d4 * 4 + q;
            float sacc = 0.f;
            const float4* wr = (const float4*)(sWo + d * 32);
#pragma unroll
            for (int j = 0; j < 8; j++) {
                float4 w = wr[j];
                sacc += u[4 * j] * w.x + u[4 * j + 1] * w.y + u[4 * j + 2] * w.z + u[4 * j + 3] * w.w;
            }
            a[q] += sacc;
        }
        hr[d4] = make_float4(a[0], a[1], a[2], a[3]);
    }
}

// ---------------- final: out = h @ w.T + b ----------------------------------
__global__ __launch_bounds__(128)
void k_final(const float* __restrict__ w, const float* __restrict__ bb,
             float* __restrict__ out) {
    __shared__ float4 sw4[4];
    __shared__ float  sb0;
    if (threadIdx.x < 4) sw4[threadIdx.x] = ((const float4*)w)[threadIdx.x];
    if (threadIdx.x == 0) sb0 = bb[0];
    __syncthreads();
    int tok = blockIdx.x * 128 + threadIdx.x;
    const float4* hr = (const float4*)(g_h + (size_t)tok * DMODEL);
    float s = sb0;
#pragma unroll
    for (int i = 0; i < 4; i++) {
        float4 v = hr[i];
        float4 w4 = sw4[i];
        s += v.x * w4.x + v.y * w4.y + v.z * w4.z + v.w * w4.w;
    }
    out[tok] = s;
}

// ---------------- driver -----------------------------------------------------
extern "C" void kernel_launch(void* const* d_in, const int* in_sizes, int n_in,
                              void* d_out, int out_size) {
    const float* x = (const float*)d_in[0];

    k_lin_in<<<NTOK / 128, 128>>>(x, (const float*)d_in[1], (const float*)d_in[2]);

    for (int layer = 0; layer < 2; layer++) {
        int o = 3 + layer * 10;
        const float* norm_w = (const float*)d_in[o + 0];
        const float* in_w   = (const float*)d_in[o + 1];
        const float* conv_w = (const float*)d_in[o + 2];
        const float* conv_b = (const float*)d_in[o + 3];
        const float* xp_w   = (const float*)d_in[o + 4];
        const float* dt_w   = (const float*)d_in[o + 5];
        const float* dt_b   = (const float*)d_in[o + 6];
        const float* A_log  = (const float*)d_in[o + 7];
        const float* Dv     = (const float*)d_in[o + 8];
        const float* out_w  = (const float*)d_in[o + 9];

        k_p1<<<NTOK / 128, 128>>>(norm_w, in_w);
        k_p2<<<dim3(LSEQ / 128, NB), 128>>>(xp_w, conv_w, conv_b, dt_w, dt_b);
        k_scan1<<<dim3(NSEG, NB), 512>>>(A_log);
        k_comb<<<NB, 512>>>();
        k_scan2<<<dim3(NSEG, NB), 512>>>(A_log);
        k_post<<<NTOK / 128, 128>>>(out_w, Dv);
    }

    k_final<<<NTOK / 128, 128>>>((const float*)d_in[23], (const float*)d_in[24],
                                 (float*)d_out);
}

// round 16
// speedup vs baseline: 1.0038x; 1.0013x over previous
#include <cuda_runtime.h>
#include <math.h>

#define NB     32
#define LSEQ   4096
#define DMODEL 16
#define DIN    32
#define NST    16
#define SEG    64
#define NSEG   (LSEQ / SEG)      // 64
#define NTOK   (NB * LSEQ)       // 131072
#define LANES  (DIN * NST)       // 512

// ---------------- device scratch (static: no allocations in kernel_launch) ----
__device__ float  g_h  [NTOK * DMODEL];   // residual stream
__device__ float  g_xin[NTOK * DIN];      // pre-conv branch
__device__ float  g_sz [NTOK * DIN];      // silu(z)
__device__ float  g_xc [NTOK * DIN];      // post-conv silu
__device__ float2 g_ddx[NTOK * DIN];      // (delta, delta*xc) per (tok, e)
__device__ float2 g_bc [NTOK * NST];      // (B, C) per (tok, n)
__device__ float  g_y  [NTOK * DIN];      // scan output
__device__ float  g_P  [NB * NSEG * LANES];
__device__ float  g_q  [NB * NSEG * LANES];
__device__ float  g_ci [NB * NSEG * LANES];

__device__ __forceinline__ float silu_f(float x) {
    return x * (1.0f / (1.0f + __expf(-x)));
}
__device__ __forceinline__ float softplus_f(float x) {
    return fmaxf(x, 0.0f) + log1pf(__expf(-fabsf(x)));
}

// ---------------- lin_in: h = x @ W.T + b   (64 -> 16) ----------------------
__global__ __launch_bounds__(128)
void k_lin_in(const float* __restrict__ x, const float* __restrict__ W,
              const float* __restrict__ bvec) {
    __shared__ float4 sW[DMODEL * 16];   // 16 rows x 64 cols
    __shared__ float  sb[DMODEL];
    int tid = threadIdx.x;
    for (int i = tid; i < DMODEL * 16; i += 128) sW[i] = ((const float4*)W)[i];
    if (tid < DMODEL) sb[tid] = bvec[tid];
    __syncthreads();

    int tok = blockIdx.x * 128 + tid;
    const float4* xr = (const float4*)(x + (size_t)tok * 64);
    float4 xv[16];
#pragma unroll
    for (int i = 0; i < 16; i++) xv[i] = xr[i];

    float4* ho = (float4*)(g_h + (size_t)tok * DMODEL);
#pragma unroll
    for (int d4 = 0; d4 < 4; d4++) {
        float a[4];
#pragma unroll
        for (int q = 0; q < 4; q++) {
            int d = d4 * 4 + q;
            float s = sb[d];
#pragma unroll
            for (int j = 0; j < 16; j++) {
                float4 w = sW[d * 16 + j];
                s += xv[j].x * w.x + xv[j].y * w.y + xv[j].z * w.z + xv[j].w * w.w;
            }
            a[q] = s;
        }
        ho[d4] = make_float4(a[0], a[1], a[2], a[3]);
    }
}

// ---------------- P1: rmsnorm + in_proj (16 -> 64), split xin / silu(z) -----
__global__ __launch_bounds__(128)
void k_p1(const float* __restrict__ norm_w, const float* __restrict__ Wi) {
    __shared__ float4 sW[64 * 4];        // 64 rows x 16 cols
    __shared__ float  snw[DMODEL];
    int tid = threadIdx.x;
    for (int i = tid; i < 64 * 4; i += 128) sW[i] = ((const float4*)Wi)[i];
    if (tid < DMODEL) snw[tid] = norm_w[tid];
    __syncthreads();

    int tok = blockIdx.x * 128 + tid;
    const float4* hr = (const float4*)(g_h + (size_t)tok * DMODEL);
    float hv[16];
#pragma unroll
    for (int i = 0; i < 4; i++) {
        float4 v = hr[i];
        hv[4 * i] = v.x; hv[4 * i + 1] = v.y; hv[4 * i + 2] = v.z; hv[4 * i + 3] = v.w;
    }
    float ss = 0.f;
#pragma unroll
    for (int d = 0; d < 16; d++) ss += hv[d] * hv[d];
    float sc = rsqrtf(ss * (1.0f / 16.0f) + 1e-5f);
    float xn[16];
#pragma unroll
    for (int d = 0; d < 16; d++) xn[d] = hv[d] * snw[d];

    float4* xin_o = (float4*)(g_xin + (size_t)tok * DIN);
    float4* sz_o  = (float4*)(g_sz  + (size_t)tok * DIN);
    float buf[4];
#pragma unroll
    for (int o = 0; o < 64; o++) {
        float s = 0.f;
#pragma unroll
        for (int j = 0; j < 4; j++) {
            float4 w = sW[o * 4 + j];
            s += xn[4 * j] * w.x + xn[4 * j + 1] * w.y + xn[4 * j + 2] * w.z + xn[4 * j + 3] * w.w;
        }
        s *= sc;
        if (o < 32) {
            buf[o & 3] = s;
            if ((o & 3) == 3) xin_o[o >> 2] = make_float4(buf[0], buf[1], buf[2], buf[3]);
        } else {
            buf[o & 3] = silu_f(s);
            if ((o & 3) == 3) sz_o[(o - 32) >> 2] = make_float4(buf[0], buf[1], buf[2], buf[3]);
        }
    }
}

// ---------------- P2: causal conv4 + silu + x_proj + softplus(delta) --------
__global__ __launch_bounds__(128)
void k_p2(const float* __restrict__ Wx, const float* __restrict__ cw,
          const float* __restrict__ cb, const float* __restrict__ dtw,
          const float* __restrict__ dtb) {
    __shared__ float4 s_xin4[131 * 8];           // 131 rows x 32 floats
    __shared__ float4 sWx4[33 * 8];              // 33 rows x 32 floats
    __shared__ float  scw[DIN * 4], scb[DIN], sdtw[DIN], sdtb[DIN];
    float* s_xin = (float*)s_xin4;
    float* sWx   = (float*)sWx4;

    int tid = threadIdx.x;
    int b = blockIdx.y;
    int t0 = blockIdx.x * 128;

    for (int i = tid; i < 33 * 8; i += 128) sWx4[i] = ((const float4*)Wx)[i];
    for (int i = tid; i < DIN * 4; i += 128) scw[i] = cw[i];
    if (tid < DIN) { scb[tid] = cb[tid]; sdtw[tid] = dtw[tid]; sdtb[tid] = dtb[tid]; }

    // stage xin rows [t0-3, t0+127] (zero-pad t<0)
    const float4* gx = (const float4*)(g_xin + ((long long)b * LSEQ + t0 - 3) * DIN);
    for (int i = tid; i < 131 * 8; i += 128) {
        float4 v;
        if (t0 == 0 && i < 24) v = make_float4(0.f, 0.f, 0.f, 0.f);
        else                   v = gx[i];
        s_xin4[i] = v;
    }
    __syncthreads();

    int t = t0 + tid;
    float xc[32];
#pragma unroll
    for (int e = 0; e < 32; e++) {
        float v = scb[e];
#pragma unroll
        for (int k = 0; k < 4; k++) v += s_xin[(tid + k) * DIN + e] * scw[e * 4 + k];
        xc[e] = silu_f(v);
    }
    size_t base = (size_t)b * LSEQ + t;

    float4* xco = (float4*)(g_xc + base * DIN);
#pragma unroll
    for (int i = 0; i < 8; i++)
        xco[i] = make_float4(xc[4 * i], xc[4 * i + 1], xc[4 * i + 2], xc[4 * i + 3]);

    float dbc[33];
#pragma unroll
    for (int o = 0; o < 33; o++) {
        float s = 0.f;
        const float4* wr = (const float4*)(sWx + o * 32);
#pragma unroll
        for (int j = 0; j < 8; j++) {
            float4 w = wr[j];
            s += xc[4 * j] * w.x + xc[4 * j + 1] * w.y + xc[4 * j + 2] * w.z + xc[4 * j + 3] * w.w;
        }
        dbc[o] = s;
    }

    float4* ddxo = (float4*)(g_ddx + base * DIN);
#pragma unroll
    for (int e = 0; e < 32; e += 2) {
        float d0 = softplus_f(dbc[0] * sdtw[e]     + sdtb[e]);
        float d1 = softplus_f(dbc[0] * sdtw[e + 1] + sdtb[e + 1]);
        ddxo[e >> 1] = make_float4(d0, d0 * xc[e], d1, d1 * xc[e + 1]);
    }
    float4* bco = (float4*)(g_bc + base * NST);
#pragma unroll
    for (int n = 0; n < 16; n += 2)
        bco[n >> 1] = make_float4(dbc[1 + n], dbc[17 + n], dbc[2 + n], dbc[18 + n]);
}

// ---------------- scan pass 1: per-segment affine map (P, q) ----------------
__global__ __launch_bounds__(512)
void k_scan1(const float* __restrict__ A_log) {
    __shared__ float4 s_ddx4[SEG * DIN / 2];    // float2[SEG*DIN]
    __shared__ float4 s_bc4 [SEG * NST / 2];
    float2* s_ddx = (float2*)s_ddx4;
    float2* s_bc  = (float2*)s_bc4;

    int tid = threadIdx.x;
    int b = blockIdx.y, s = blockIdx.x;
    size_t base = (size_t)b * LSEQ + (size_t)s * SEG;

    const float4* gd = (const float4*)(g_ddx + base * DIN);
#pragma unroll
    for (int i = tid; i < SEG * DIN / 2; i += 512) s_ddx4[i] = gd[i];
    const float4* gb = (const float4*)(g_bc + base * NST);
#pragma unroll
    for (int i = tid; i < SEG * NST / 2; i += 512) s_bc4[i] = gb[i];

    int e = tid >> 4, n = tid & 15;
    float Aen = -expf(A_log[e * NST + n]);
    __syncthreads();

    float h = 0.f, P = 1.f;
#pragma unroll 4
    for (int t = 0; t < SEG; t++) {
        float2 dd = s_ddx[t * DIN + e];
        float2 bc = s_bc[t * NST + n];
        float dA = __expf(dd.x * Aen);
        h = fmaf(dA, h, dd.y * bc.x);
        P *= dA;
    }
    int li = (b * NSEG + s) * LANES + tid;
    g_P[li] = P;
    g_q[li] = h;
}

// ---------------- combine carries across segments ---------------------------
__global__ __launch_bounds__(512)
void k_comb() {
    int b = blockIdx.x, tid = threadIdx.x;
    float h = 0.f;
    for (int s = 0; s < NSEG; s++) {
        int li = (b * NSEG + s) * LANES + tid;
        g_ci[li] = h;
        h = g_P[li] * h + g_q[li];
    }
}

// ---------------- scan pass 2: full scan with carry, emit y -----------------
__global__ __launch_bounds__(512)
void k_scan2(const float* __restrict__ A_log) {
    __shared__ float4 s_ddx4[SEG * DIN / 2];
    __shared__ float4 s_bc4 [SEG * NST / 2];
    __shared__ float4 s_y4  [SEG * DIN / 4];
    float2* s_ddx = (float2*)s_ddx4;
    float2* s_bc  = (float2*)s_bc4;
    float*  s_y   = (float*)s_y4;

    int tid = threadIdx.x;
    int b = blockIdx.y, s = blockIdx.x;
    size_t base = (size_t)b * LSEQ + (size_t)s * SEG;

    const float4* gd = (const float4*)(g_ddx + base * DIN);
#pragma unroll
    for (int i = tid; i < SEG * DIN / 2; i += 512) s_ddx4[i] = gd[i];
    const float4* gb = (const float4*)(g_bc + base * NST);
#pragma unroll
    for (int i = tid; i < SEG * NST / 2; i += 512) s_bc4[i] = gb[i];

    int e = tid >> 4, n = tid & 15;
    float Aen = -expf(A_log[e * NST + n]);
    float h = g_ci[(b * NSEG + s) * LANES + tid];
    __syncthreads();

#pragma unroll 2
    for (int t = 0; t < SEG; t++) {
        float2 dd = s_ddx[t * DIN + e];
        float2 bc = s_bc[t * NST + n];
        float dA = __expf(dd.x * Aen);
        h = fmaf(dA, h, dd.y * bc.x);
        float p = h * bc.y;
        p += __shfl_xor_sync(0xffffffffu, p, 8);
        p += __shfl_xor_sync(0xffffffffu, p, 4);
        p += __shfl_xor_sync(0xffffffffu, p, 2);
        p += __shfl_xor_sync(0xffffffffu, p, 1);
        if (n == 0) s_y[t * DIN + e] = p;
    }
    __syncthreads();

    float4* gy = (float4*)(g_y + base * DIN);
#pragma unroll
    for (int i = tid; i < SEG * DIN / 4; i += 512) gy[i] = s_y4[i];
}

// ---------------- post: (y + D*xc) * silu(z) @ Wo.T + residual --------------
__global__ __launch_bounds__(128)
void k_post(const float* __restrict__ Wo, const float* __restrict__ Dv) {
    __shared__ float4 sWo4[DMODEL * 8];   // 16 rows x 32 cols
    __shared__ float  sD[DIN];
    float* sWo = (float*)sWo4;
    int tid = threadIdx.x;
    for (int i = tid; i < DMODEL * 8; i += 128) sWo4[i] = ((const float4*)Wo)[i];
    if (tid < DIN) sD[tid] = Dv[tid];
    __syncthreads();

    int tok = blockIdx.x * 128 + tid;
    size_t b32 = (size_t)tok * DIN;
    const float4* yr  = (const float4*)(g_y  + b32);
    const float4* xcr = (const float4*)(g_xc + b32);
    const float4* szr = (const float4*)(g_sz + b32);
    float u[32];
#pragma unroll
    for (int i = 0; i < 8; i++) {
        float4 y = yr[i], xc = xcr[i], sz = szr[i];
        u[4 * i + 0] = (y.x + sD[4 * i + 0] * xc.x) * sz.x;
        u[4 * i + 1] = (y.y + sD[4 * i + 1] * xc.y) * sz.y;
        u[4 * i + 2] = (y.z + sD[4 * i + 2] * xc.z) * sz.z;
        u[4 * i + 3] = (y.w + sD[4 * i + 3] * xc.w) * sz.w;
    }
    float4* hr = (float4*)(g_h + (size_t)tok * DMODEL);
#pragma unroll
    for (int d4 = 0; d4 < 4; d4++) {
        float4 hv = hr[d4];
        float a[4] = {hv.x, hv.y, hv.z, hv.w};
#pragma unroll
        for (int q = 0; q < 4; q++) {
            int d = d4 * 4 + q;
            float sacc = 0.f;
            const float4* wr = (const float4*)(sWo + d * 32);
#pragma unroll
            for (int j = 0; j < 8; j++) {
                float4 w = wr[j];
                sacc += u[4 * j] * w.x + u[4 * j + 1] * w.y + u[4 * j + 2] * w.z + u[4 * j + 3] * w.w;
            }
            a[q] += sacc;
        }
        hr[d4] = make_float4(a[0], a[1], a[2], a[3]);
    }
}

// ---------------- final: out = h @ w.T + b ----------------------------------
__global__ __launch_bounds__(128)
void k_final(const float* __restrict__ w, const float* __restrict__ bb,
             float* __restrict__ out) {
    __shared__ float4 sw4[4];
    __shared__ float  sb0;
    if (threadIdx.x < 4) sw4[threadIdx.x] = ((const float4*)w)[threadIdx.x];
    if (threadIdx.x == 0) sb0 = bb[0];
    __syncthreads();
    int tok = blockIdx.x * 128 + threadIdx.x;
    const float4* hr = (const float4*)(g_h + (size_t)tok * DMODEL);
    float s = sb0;
#pragma unroll
    for (int i = 0; i < 4; i++) {
        float4 v = hr[i];
        float4 w4 = sw4[i];
        s += v.x * w4.x + v.y * w4.y + v.z * w4.z + v.w * w4.w;
    }
    out[tok] = s;
}

// ---------------- driver -----------------------------------------------------
extern "C" void kernel_launch(void* const* d_in, const int* in_sizes, int n_in,
                              void* d_out, int out_size) {
    const float* x = (const float*)d_in[0];

    k_lin_in<<<NTOK / 128, 128>>>(x, (const float*)d_in[1], (const float*)d_in[2]);

    for (int layer = 0; layer < 2; layer++) {
        int o = 3 + layer * 10;
        const float* norm_w = (const float*)d_in[o + 0];
        const float* in_w   = (const float*)d_in[o + 1];
        const float* conv_w = (const float*)d_in[o + 2];
        const float* conv_b = (const float*)d_in[o + 3];
        const float* xp_w   = (const float*)d_in[o + 4];
        const float* dt_w   = (const float*)d_in[o + 5];
        const float* dt_b   = (const float*)d_in[o + 6];
        const float* A_log  = (const float*)d_in[o + 7];
        const float* Dv     = (const float*)d_in[o + 8];
        const float* out_w  = (const float*)d_in[o + 9];

        k_p1<<<NTOK / 128, 128>>>(norm_w, in_w);
        k_p2<<<dim3(LSEQ / 128, NB), 128>>>(xp_w, conv_w, conv_b, dt_w, dt_b);
        k_scan1<<<dim3(NSEG, NB), 512>>>(A_log);
        k_comb<<<NB, 512>>>();
        k_scan2<<<dim3(NSEG, NB), 512>>>(A_log);
        k_post<<<NTOK / 128, 128>>>(out_w, Dv);
    }

    k_final<<<NTOK / 128, 128>>>((const float*)d_in[23], (const float*)d_in[24],
                                 (float*)d_out);
}